// round 3
// baseline (speedup 1.0000x reference)
#include <cuda_runtime.h>

// ---------------------------------------------------------------------------
// Persistent fused LSTM: T=2048, B=256, H=128, IN_DIM=1, output feedback.
// 128 CTAs x 256 threads; CTA c owns batches (2c, 2c+1) end-to-end.
// Weights W_hh: rows 0..255 (i,f gates) in registers, rows 256..511 (g,o)
// in bank-padded SMEM (fp32). Packed fma.rn.f32x2 for 2x fp32 throughput.
// R2 fix: bias + x*W_ih contribution counted once (ks==0 lane only), not
// twice across the complementary k-half lanes.
// ---------------------------------------------------------------------------

typedef unsigned long long ull;

// SMEM layout (float offsets)
#define WS_OFF   0            // 256 rows x padded(132) = 33792 floats (128KB weights, padded)
#define GBUF     33792        // gates staging: 2 batches x 512
#define HBUF     34816        // h: 2 batches x padded(136)
#define WLIN     35088        // W_lin row: 128
#define YBUF     35216        // per-warp y partials: 8
#define XBUF     35224        // fed-back x per batch: 2
#define SMEM_FLOATS 35232
#define SMEM_BYTES  (SMEM_FLOATS * 4)

#define T_STEPS 2048
#define NB      256

__device__ __forceinline__ ull pk2(float x, float y) {
    ull r;
    asm("mov.b64 %0, {%1, %2};" : "=l"(r) : "f"(x), "f"(y));
    return r;
}
__device__ __forceinline__ float2 upk2(ull v) {
    float2 f;
    asm("mov.b64 {%0, %1}, %2;" : "=f"(f.x), "=f"(f.y) : "l"(v));
    return f;
}
// Packed dual-fp32 FMA (Blackwell f32x2 pipe). ptxas never emits this on its
// own; inline PTX is the only route. 2x FLOPs vs scalar FFMA.
__device__ __forceinline__ ull ffma2(ull a, ull b, ull c) {
    ull d;
    asm("fma.rn.f32x2 %0, %1, %2, %3;" : "=l"(d) : "l"(a), "l"(b), "l"(c));
    return d;
}

__device__ __forceinline__ float sigf(float x)  { return __fdividef(1.0f, 1.0f + __expf(-x)); }
__device__ __forceinline__ float tanhx(float x) { return __fdividef(2.0f, 1.0f + __expf(-2.0f * x)) - 1.0f; }

// padded smem addressing: row pitch 132 floats, k-half offset 68 floats.
__device__ __forceinline__ int ws_idx(int row, int k) {
    return WS_OFF + row * 132 + (k >> 6) * 68 + (k & 63);
}
__device__ __forceinline__ int hb_idx(int b, int k) {
    return HBUF + b * 136 + (k >> 6) * 68 + (k & 63);
}

__global__ void __launch_bounds__(256, 1)
lstm_seq_kernel(float* __restrict__ out,
                const int*   __restrict__ label,
                const float* __restrict__ h0,
                const float* __restrict__ W_ih,
                const float* __restrict__ W_hh,
                const float* __restrict__ b_ih,
                const float* __restrict__ b_hh,
                const float* __restrict__ W_lin,
                const float* __restrict__ b_lin)
{
    extern __shared__ float sm[];
    const int t   = threadIdx.x;
    const int cta = blockIdx.x;
    const int p   = t >> 1;      // row pair 0..127
    const int ks  = t & 1;       // k half: [0,64) or [64,128)
    const int kofs  = ks * 68;   // padded k offset
    const int kbase = ks * 64;
    // bias/input term belongs to exactly ONE of the two k-half lanes
    const float bsel = ks ? 0.0f : 1.0f;

    // ---- one-time init -----------------------------------------------------
    for (int idx = t; idx < 256 * 128; idx += 256) {
        int row = idx >> 7;
        int k   = idx & 127;
        sm[ws_idx(row, k)] = W_hh[(256 + row) * 128 + k];
    }
    if (t < 128) sm[WLIN + t] = W_lin[t];
    {   // initial h from h0[0, label[b], :]
        int b = t >> 7, j = t & 127;
        int lab = label[2 * cta + b];
        sm[hb_idx(b, j)] = h0[lab * 128 + j];
    }
    if (t < 2) sm[XBUF + t] = 0.0f;

    // Register weights: rows 2p, 2p+1 (gates i,f), this thread's k half.
    float4 wreg[2][16];
#pragma unroll
    for (int rr = 0; rr < 2; ++rr) {
        const float4* wsrc = (const float4*)(W_hh + (2 * p + rr) * 128 + kbase);
#pragma unroll
        for (int c = 0; c < 16; ++c) wreg[rr][c] = wsrc[c];
    }

    // bias + W_ih for this thread's 4 gate rows: {2p, 2p+1, 256+2p, 257+2p}
    float biasv[4], wihv[4];
    {
        int rows[4] = {2 * p, 2 * p + 1, 256 + 2 * p, 257 + 2 * p};
#pragma unroll
        for (int q = 0; q < 4; ++q) {
            biasv[q] = b_ih[rows[q]] + b_hh[rows[q]];
            wihv[q]  = W_ih[rows[q]];
        }
    }
    const float blin = b_lin[0];
    float c_state = 0.0f;   // cell state for (b = t>>7, j = t&127)

    __syncthreads();

    // ---- 2048-step recurrence ----------------------------------------------
    for (int step = 0; step < T_STEPS; ++step) {
        // ====== matvec phase: gates = W_hh h + x W_ih + b ======
        float x0 = sm[XBUF + 0];
        float x1 = sm[XBUF + 1];

        ull acc[4][2];
#pragma unroll
        for (int q = 0; q < 4; ++q) {
            // only the ks==0 lane carries the bias + x*W_ih term (the shfl_xor
            // below sums both k-half lanes; counting it twice was the R1 bug)
            acc[q][0] = pk2(bsel * fmaf(x0, wihv[q], biasv[q]), 0.0f);
            acc[q][1] = pk2(bsel * fmaf(x1, wihv[q], biasv[q]), 0.0f);
        }

        const float* wsm0 = sm + WS_OFF + (2 * p) * 132 + kofs;  // smem row 256+2p
        const float* wsm1 = wsm0 + 132;                           // smem row 257+2p
        const float* hp0  = sm + HBUF + kofs;                     // h batch 0
        const float* hp1  = hp0 + 136;                            // h batch 1

#pragma unroll
        for (int c = 0; c < 16; ++c) {
            float4 hv0 = *(const float4*)(hp0 + c * 4);
            float4 hv1 = *(const float4*)(hp1 + c * 4);
            float4 wv0 = wreg[0][c];
            float4 wv1 = wreg[1][c];
            float4 wv2 = *(const float4*)(wsm0 + c * 4);
            float4 wv3 = *(const float4*)(wsm1 + c * 4);

            ull h0a = pk2(hv0.x, hv0.y), h0b = pk2(hv0.z, hv0.w);
            ull h1a = pk2(hv1.x, hv1.y), h1b = pk2(hv1.z, hv1.w);
            ull w0a = pk2(wv0.x, wv0.y), w0b = pk2(wv0.z, wv0.w);
            ull w1a = pk2(wv1.x, wv1.y), w1b = pk2(wv1.z, wv1.w);
            ull w2a = pk2(wv2.x, wv2.y), w2b = pk2(wv2.z, wv2.w);
            ull w3a = pk2(wv3.x, wv3.y), w3b = pk2(wv3.z, wv3.w);

#define DO_ROW(q, wa, wb)                                   \
            acc[q][0] = ffma2(wa, h0a, acc[q][0]);          \
            acc[q][0] = ffma2(wb, h0b, acc[q][0]);          \
            acc[q][1] = ffma2(wa, h1a, acc[q][1]);          \
            acc[q][1] = ffma2(wb, h1b, acc[q][1]);
            DO_ROW(0, w0a, w0b)
            DO_ROW(1, w1a, w1b)
            DO_ROW(2, w2a, w2b)
            DO_ROW(3, w3a, w3b)
#undef DO_ROW
        }

        // reduce f32x2 lanes + combine complementary k halves (partner = t^1)
        float s[4][2];
#pragma unroll
        for (int q = 0; q < 4; ++q) {
#pragma unroll
            for (int b = 0; b < 2; ++b) {
                float2 a = upk2(acc[q][b]);
                float v = a.x + a.y;
                v += __shfl_xor_sync(0xffffffffu, v, 1);
                s[q][b] = v;
            }
        }
        {   // ks=0 lane writes rows 2p,2p+1 ; ks=1 lane writes 256+2p,257+2p
            int rbase = ks ? (256 + 2 * p) : (2 * p);
            int qb    = ks ? 2 : 0;
#pragma unroll
            for (int rr = 0; rr < 2; ++rr)
#pragma unroll
                for (int b = 0; b < 2; ++b)
                    sm[GBUF + b * 512 + rbase + rr] = s[qb + rr][b];
        }
        __syncthreads();

        // ====== update phase: c,h,y for (b = t>>7, j = t&127) ======
        {
            int b = t >> 7, j = t & 127;
            const float* gb = sm + GBUF + b * 512 + j;
            float gi = gb[0], gf = gb[128], gg = gb[256], go = gb[384];
            float iv = sigf(gi);
            float fv = sigf(gf);
            float gv = tanhx(gg);
            float ov = sigf(go);
            c_state = fv * c_state + iv * gv;
            float hn = ov * tanhx(c_state);
            sm[hb_idx(b, j)] = hn;

            float py = hn * sm[WLIN + j];
#pragma unroll
            for (int off = 16; off; off >>= 1)
                py += __shfl_down_sync(0xffffffffu, py, off);
            if ((t & 31) == 0) sm[YBUF + (t >> 5)] = py;
        }
        __syncthreads();

        if (t < 2) {
            float y = sm[YBUF + 4 * t] + sm[YBUF + 4 * t + 1] +
                      sm[YBUF + 4 * t + 2] + sm[YBUF + 4 * t + 3] + blin;
            sm[XBUF + t] = y;                         // feedback input
            out[step * NB + 2 * cta + t] = y;         // ys[t, b, 0]
        }
        __syncthreads();
    }
}

extern "C" void kernel_launch(void* const* d_in, const int* in_sizes, int n_in,
                              void* d_out, int out_size) {
    // metadata order: input, label, h0, W_ih, W_hh, b_ih, b_hh, W_lin, b_lin
    const int*   label  = (const int*)  d_in[1];
    const float* h0     = (const float*)d_in[2];
    const float* W_ih   = (const float*)d_in[3];
    const float* W_hh   = (const float*)d_in[4];
    const float* b_ih   = (const float*)d_in[5];
    const float* b_hh   = (const float*)d_in[6];
    const float* W_lin  = (const float*)d_in[7];
    const float* b_lin  = (const float*)d_in[8];
    float* out = (float*)d_out;

    cudaFuncSetAttribute(lstm_seq_kernel,
                         cudaFuncAttributeMaxDynamicSharedMemorySize, SMEM_BYTES);
    lstm_seq_kernel<<<128, 256, SMEM_BYTES>>>(out, label, h0, W_ih, W_hh,
                                              b_ih, b_hh, W_lin, b_lin);
}